// round 1
// baseline (speedup 1.0000x reference)
#include <cuda_runtime.h>
#include <cuda_bf16.h>
#include <math.h>

// Problem constants
#define BB   8
#define LL   128
#define SS   100
#define TT   100
#define QD   512
#define FD   2048
#define HD   512
#define OD   512

// Scratch (device globals; no allocations allowed)
__device__ float g_q[BB * LL * HD];        // 1024 x 512
__device__ float g_key[(BB*SS + BB*TT) * HD]; // 1600 x 512 : rows [0,800)=s_key, [800,1600)=t_key
__device__ float g_ctx[BB * LL * HD];      // 1024 x 512

// ---------------------------------------------------------------------------
// Generic tiled fp32 GEMM: C[M,N] = A @ W + bias
//   A element (r,c):
//     colSplit == 0: row-split  -> r <  rowSplit: A0[r*K + c], else A1[(r-rowSplit)*K + c]
//     colSplit  > 0: col-split  -> c < colSplit: A0[r*colSplit + c], else A1[r*(K-colSplit) + c - colSplit]
//   W is K x N row-major. 64x64 block tile, BK=16, 256 threads, 4x4 per-thread.
// ---------------------------------------------------------------------------
__global__ __launch_bounds__(256) void gemm64(
    const float* __restrict__ A0, const float* __restrict__ A1,
    int rowSplit, int colSplit,
    const float* __restrict__ W, const float* __restrict__ bias,
    float* __restrict__ C, int M, int N, int K)
{
    const int bm = blockIdx.y * 64;
    const int bn = blockIdx.x * 64;
    const int tid = threadIdx.x;
    const int tx = tid & 15;        // 0..15  (N direction)
    const int ty = tid >> 4;        // 0..15  (M direction)

    __shared__ float As[16][65];    // [k][m], padded
    __shared__ float Bs[16][64];    // [k][n]

    float acc[4][4];
#pragma unroll
    for (int i = 0; i < 4; i++)
#pragma unroll
        for (int j = 0; j < 4; j++) acc[i][j] = 0.f;

    for (int k0 = 0; k0 < K; k0 += 16) {
        // Load A tile: 64 rows x 16 cols
#pragma unroll
        for (int it = 0; it < 4; it++) {
            int idx = tid + 256 * it;
            int r = idx >> 4;       // 0..63
            int c = idx & 15;       // 0..15
            int gr = bm + r;
            int gc = k0 + c;
            float v;
            if (colSplit > 0) {
                v = (gc < colSplit) ? A0[(long)gr * colSplit + gc]
                                    : A1[(long)gr * (K - colSplit) + (gc - colSplit)];
            } else {
                v = (gr < rowSplit) ? A0[(long)gr * K + gc]
                                    : A1[(long)(gr - rowSplit) * K + gc];
            }
            As[c][r] = v;
        }
        // Load B tile: 16 rows x 64 cols (coalesced)
#pragma unroll
        for (int it = 0; it < 4; it++) {
            int idx = tid + 256 * it;
            int r = idx >> 6;       // 0..15
            int c = idx & 63;       // 0..63
            Bs[r][c] = W[(long)(k0 + r) * N + bn + c];
        }
        __syncthreads();

#pragma unroll
        for (int k = 0; k < 16; k++) {
            float a[4], b[4];
#pragma unroll
            for (int i = 0; i < 4; i++) a[i] = As[k][ty * 4 + i];
#pragma unroll
            for (int j = 0; j < 4; j++) b[j] = Bs[k][tx * 4 + j];
#pragma unroll
            for (int i = 0; i < 4; i++)
#pragma unroll
                for (int j = 0; j < 4; j++) acc[i][j] = fmaf(a[i], b[j], acc[i][j]);
        }
        __syncthreads();
    }

#pragma unroll
    for (int i = 0; i < 4; i++) {
        int gr = bm + ty * 4 + i;
#pragma unroll
        for (int j = 0; j < 4; j++) {
            int gc = bn + tx * 4 + j;
            C[(long)gr * N + gc] = acc[i][j] + bias[gc];
        }
    }
}

// ---------------------------------------------------------------------------
// Fused attention middle:
//   per (b, l): qs[s] = q.s_key[s], qt[t] = q.t_key[t]
//   ws = softmax_s(qs/32), wt = softmax_t(-qt/32)     [joint softmax factorizes]
//   ctx = (ws @ s_key - wt @ t_key) / sqrt(2)
// Block: (ltile of 8 l's) x batch. 256 threads. Keys staged via smem k-tiles.
// ---------------------------------------------------------------------------
#define LT 8
#define NK 200          // 100 s-keys + 100 t-keys
#define KT 32           // k-tile width
#define NKT (HD / KT)   // 16 tiles

__global__ __launch_bounds__(256) void attn_kernel(
    const float* __restrict__ gq, const float* __restrict__ gkey,
    float* __restrict__ gctx)
{
    const int b  = blockIdx.y;
    const int l0 = blockIdx.x * LT;
    const int tid = threadIdx.x;
    const int lane = tid & 31;
    const int wid  = tid >> 5;   // 0..7 == local l

    __shared__ float sm_k[NK][KT + 1];   // padded
    __shared__ float sm_qs[LT][KT];
    __shared__ float sm_sc[LT][NK];
    __shared__ float sm_w[LT][NK];

    const float* keyS = gkey + (long)(b * SS) * HD;           // s_key rows
    const float* keyT = gkey + (long)(BB * SS + b * TT) * HD; // t_key rows

    // ---------- Phase 1+2: score accumulation over k-tiles ----------
    float acc[LT];
#pragma unroll
    for (int l = 0; l < LT; l++) acc[l] = 0.f;

    for (int kt = 0; kt < NKT; kt++) {
        // q slice: 8 x 32 = 256 elems -> 1 per thread
        {
            int l = tid >> 5, c = tid & 31;
            sm_qs[l][c] = gq[(long)(b * LL + l0 + l) * HD + kt * KT + c];
        }
        // key tile: 200 x 32
        for (int i = tid; i < NK * KT; i += 256) {
            int r = i >> 5, c = i & 31;
            const float* srcp = (r < SS) ? (keyS + (long)r * HD)
                                         : (keyT + (long)(r - SS) * HD);
            sm_k[r][c] = srcp[kt * KT + c];
        }
        __syncthreads();

        if (tid < NK) {
#pragma unroll 8
            for (int k = 0; k < KT; k++) {
                float kv = sm_k[tid][k];
#pragma unroll
                for (int l = 0; l < LT; l++) acc[l] = fmaf(kv, sm_qs[l][k], acc[l]);
            }
        }
        __syncthreads();
    }

    if (tid < NK) {
#pragma unroll
        for (int l = 0; l < LT; l++) sm_sc[l][tid] = acc[l];
    }
    __syncthreads();

    // ---------- Phase 3: factorized softmax (one warp per l) ----------
    {
        const int l = wid;
        const float sc1 = 1.0f / 32.0f;          // 1/sqrt(2*HD)
        const float rs2 = 0.70710678118654752f;  // 1/sqrt(2)

        // s-part: ws = softmax_s(qs * sc1)
        float vb[4], m = -1e30f;
#pragma unroll
        for (int ii = 0; ii < 4; ii++) {
            int j = lane + 32 * ii;
            vb[ii] = (j < SS) ? sm_sc[l][j] * sc1 : -1e30f;
            m = fmaxf(m, vb[ii]);
        }
#pragma unroll
        for (int off = 16; off; off >>= 1) m = fmaxf(m, __shfl_xor_sync(0xffffffffu, m, off));
        float sum = 0.f;
#pragma unroll
        for (int ii = 0; ii < 4; ii++) {
            int j = lane + 32 * ii;
            if (j < SS) { float e = __expf(vb[ii] - m); sm_w[l][j] = e; sum += e; }
        }
#pragma unroll
        for (int off = 16; off; off >>= 1) sum += __shfl_xor_sync(0xffffffffu, sum, off);
        float inv = rs2 / sum;
#pragma unroll
        for (int ii = 0; ii < 4; ii++) {
            int j = lane + 32 * ii;
            if (j < SS) sm_w[l][j] *= inv;
        }

        // t-part: wt = softmax_t(-qt * sc1), contributes with minus sign
        m = -1e30f;
#pragma unroll
        for (int ii = 0; ii < 4; ii++) {
            int j = lane + 32 * ii;
            vb[ii] = (j < TT) ? -sm_sc[l][SS + j] * sc1 : -1e30f;
            m = fmaxf(m, vb[ii]);
        }
#pragma unroll
        for (int off = 16; off; off >>= 1) m = fmaxf(m, __shfl_xor_sync(0xffffffffu, m, off));
        sum = 0.f;
#pragma unroll
        for (int ii = 0; ii < 4; ii++) {
            int j = lane + 32 * ii;
            if (j < TT) { float e = __expf(vb[ii] - m); sm_w[l][SS + j] = e; sum += e; }
        }
#pragma unroll
        for (int off = 16; off; off >>= 1) sum += __shfl_xor_sync(0xffffffffu, sum, off);
        inv = -rs2 / sum;
#pragma unroll
        for (int ii = 0; ii < 4; ii++) {
            int j = lane + 32 * ii;
            if (j < TT) sm_w[l][SS + j] *= inv;
        }
    }
    __syncthreads();

    // ---------- Phase 4: ctx = weights @ keys, tile by tile ----------
    for (int kt = 0; kt < NKT; kt++) {
        for (int i = tid; i < NK * KT; i += 256) {
            int r = i >> 5, c = i & 31;
            const float* srcp = (r < SS) ? (keyS + (long)r * HD)
                                         : (keyT + (long)(r - SS) * HD);
            sm_k[r][c] = srcp[kt * KT + c];
        }
        __syncthreads();

        const int l = wid;
        float a0 = 0.f;
#pragma unroll 8
        for (int j = 0; j < NK; j++) a0 = fmaf(sm_w[l][j], sm_k[j][lane], a0);
        gctx[(long)(b * LL + l0 + l) * HD + kt * KT + lane] = a0;
        __syncthreads();
    }
}

// ---------------------------------------------------------------------------
extern "C" void kernel_launch(void* const* d_in, const int* in_sizes, int n_in,
                              void* d_out, int out_size)
{
    const float* query = (const float*)d_in[0];  // (8,128,512)
    const float* src   = (const float*)d_in[1];  // (8,100,2048)
    const float* trg   = (const float*)d_in[2];  // (8,100,2048)
    const float* Wq    = (const float*)d_in[3];  // (512,512)
    const float* bq    = (const float*)d_in[4];  // (512)
    const float* Ws    = (const float*)d_in[5];  // (2048,512)
    const float* bs    = (const float*)d_in[6];  // (512)
    const float* Wo    = (const float*)d_in[7];  // (1024,512)
    const float* bo    = (const float*)d_in[8];  // (512)
    float* out = (float*)d_out;                  // (8,128,512)

    float *qbuf, *keybuf, *ctxbuf;
    cudaGetSymbolAddress((void**)&qbuf,   g_q);
    cudaGetSymbolAddress((void**)&keybuf, g_key);
    cudaGetSymbolAddress((void**)&ctxbuf, g_ctx);

    // q = query @ Wq + bq : M=1024, N=512, K=512
    gemm64<<<dim3(HD / 64, (BB * LL) / 64), 256>>>(
        query, query, 1 << 30, 0, Wq, bq, qbuf, BB * LL, HD, QD);

    // keys = [src; trg] @ Ws + bs : M=1600, N=512, K=2048 (row-split at 800)
    gemm64<<<dim3(HD / 64, (BB * (SS + TT)) / 64), 256>>>(
        src, trg, BB * SS, 0, Ws, bs, keybuf, BB * (SS + TT), HD, FD);

    // attention middle (factorized softmax) -> ctx
    attn_kernel<<<dim3(LL / LT, BB), 256>>>(qbuf, keybuf, ctxbuf);

    // out = [query, ctx] @ Wo + bo : M=1024, N=512, K=1024 (col-split at 512)
    gemm64<<<dim3(OD / 64, (BB * LL) / 64), 256>>>(
        query, ctxbuf, 0, QD, Wo, bo, out, BB * LL, OD, QD + HD);
}

// round 2
// speedup vs baseline: 1.3749x; 1.3749x over previous
#include <cuda_runtime.h>
#include <cuda_bf16.h>
#include <mma.h>
#include <math.h>

using namespace nvcuda;

// Problem constants
#define BB   8
#define LL   128
#define SS   100
#define TT   100
#define QD   512
#define FD   2048
#define HD   512
#define OD   512

// Scratch (device globals; no allocations allowed)
__device__ float g_q[BB * LL * HD];
__device__ float g_key[(BB*SS + BB*TT) * HD];   // rows [0,800)=s_key, [800,1600)=t_key
__device__ float g_ctx[BB * LL * HD];

// ---------------------------------------------------------------------------
// tf32 wmma GEMM: C[M,N] = A @ W + bias
//   A addressing:
//     colSplit == 0 : row-split  -> row r <  rowSplit: A0[r*K+c], else A1[(r-rowSplit)*K+c]
//     colSplit  > 0 : col-split  -> col c < colSplit: A0[r*colSplit+c], else A1[r*(K-colSplit)+c-colSplit]
//       (colSplit must be a multiple of 32 so a BK-tile never straddles)
//   64x64 block tile, BK=32, 128 threads = 4 warps of 32x32 warp tiles.
//   Double-buffered smem, register-staged gmem prefetch, one sync per K-tile.
// ---------------------------------------------------------------------------
struct GemmDesc {
    const float* A0; const float* A1;
    int rowSplit;
    int colSplit;
    const float* W; const float* bias;
    float* C;
    int N, K;
    int tilesN;
};

#define LDA 40
#define LDB 72
#define LDC 68
#define A_SM (64 * LDA)   // 2560 floats
#define B_SM (32 * LDB)   // 2304 floats

__global__ __launch_bounds__(128) void gemm_tc(GemmDesc ga, GemmDesc gb, int tilesA)
{
    __shared__ float smem[2 * A_SM + 2 * B_SM];

    const bool first = (blockIdx.x < (unsigned)tilesA);
    GemmDesc g = first ? ga : gb;
    const int bid = first ? blockIdx.x : blockIdx.x - tilesA;

    const int bm = (bid / g.tilesN) * 64;
    const int bn = (bid % g.tilesN) * 64;
    const int tid = threadIdx.x;
    const int wid = tid >> 5;
    const int wm = (wid >> 1) * 32;   // warp row offset in tile
    const int wn = (wid & 1) * 32;    // warp col offset in tile

    wmma::fragment<wmma::accumulator, 16, 16, 8, float> cf[2][2];
#pragma unroll
    for (int i = 0; i < 2; i++)
#pragma unroll
        for (int j = 0; j < 2; j++) wmma::fill_fragment(cf[i][j], 0.0f);

    float4 pa[4], pb[4];

    // ---- gmem prefetch of tile k0 into registers ----
    auto prefetch = [&](int k0) {
#pragma unroll
        for (int i = 0; i < 4; i++) {
            int idx = tid + 128 * i;
            int r = idx >> 3, c4 = idx & 7;
            int gr = bm + r, gc = k0 + c4 * 4;
            const float* p;
            if (g.colSplit) {
                if (gc < g.colSplit) p = g.A0 + (long)gr * g.colSplit + gc;
                else                 p = g.A1 + (long)gr * (g.K - g.colSplit) + (gc - g.colSplit);
            } else {
                if (gr < g.rowSplit) p = g.A0 + (long)gr * g.K + gc;
                else                 p = g.A1 + (long)(gr - g.rowSplit) * g.K + gc;
            }
            pa[i] = *(const float4*)p;
        }
#pragma unroll
        for (int i = 0; i < 4; i++) {
            int idx = tid + 128 * i;
            int r = idx >> 4, c4 = idx & 15;
            pb[i] = *(const float4*)(g.W + (long)(k0 + r) * g.N + bn + c4 * 4);
        }
    };

    prefetch(0);
    int buf = 0;

    for (int k0 = 0; k0 < g.K; k0 += 32) {
        float* As = smem + buf * A_SM;
        float* Bs = smem + 2 * A_SM + buf * B_SM;

        // regs -> smem
#pragma unroll
        for (int i = 0; i < 4; i++) {
            int idx = tid + 128 * i;
            int r = idx >> 3, c4 = idx & 7;
            *(float4*)&As[r * LDA + c4 * 4] = pa[i];
        }
#pragma unroll
        for (int i = 0; i < 4; i++) {
            int idx = tid + 128 * i;
            int r = idx >> 4, c4 = idx & 15;
            *(float4*)&Bs[r * LDB + c4 * 4] = pb[i];
        }
        __syncthreads();

        if (k0 + 32 < g.K) prefetch(k0 + 32);

        // compute from smem[buf]
#pragma unroll
        for (int k = 0; k < 32; k += 8) {
            wmma::fragment<wmma::matrix_a, 16, 16, 8, wmma::precision::tf32, wmma::row_major> af[2];
            wmma::fragment<wmma::matrix_b, 16, 16, 8, wmma::precision::tf32, wmma::row_major> bf[2];
#pragma unroll
            for (int i = 0; i < 2; i++) {
                wmma::load_matrix_sync(af[i], &As[(wm + 16 * i) * LDA + k], LDA);
#pragma unroll
                for (int t = 0; t < af[i].num_elements; t++)
                    af[i].x[t] = wmma::__float_to_tf32(af[i].x[t]);
            }
#pragma unroll
            for (int j = 0; j < 2; j++) {
                wmma::load_matrix_sync(bf[j], &Bs[k * LDB + wn + 16 * j], LDB);
#pragma unroll
                for (int t = 0; t < bf[j].num_elements; t++)
                    bf[j].x[t] = wmma::__float_to_tf32(bf[j].x[t]);
            }
#pragma unroll
            for (int i = 0; i < 2; i++)
#pragma unroll
                for (int j = 0; j < 2; j++)
                    wmma::mma_sync(cf[i][j], af[i], bf[j], cf[i][j]);
        }
        buf ^= 1;
    }

    // ---- epilogue: stage C through smem, add bias, coalesced store ----
    __syncthreads();
    float* Cst = smem;   // reuse (64*68 = 4352 floats, fits)
#pragma unroll
    for (int i = 0; i < 2; i++)
#pragma unroll
        for (int j = 0; j < 2; j++)
            wmma::store_matrix_sync(&Cst[(wm + 16 * i) * LDC + wn + 16 * j],
                                    cf[i][j], LDC, wmma::mem_row_major);
    __syncthreads();

#pragma unroll
    for (int i = 0; i < 8; i++) {
        int idx = tid + 128 * i;
        int r = idx >> 4, c4 = idx & 15;
        float4 v = *(float4*)&Cst[r * LDC + c4 * 4];
        float4 b4 = *(const float4*)&g.bias[bn + c4 * 4];
        v.x += b4.x; v.y += b4.y; v.z += b4.z; v.w += b4.w;
        *(float4*)&g.C[(long)(bm + r) * g.N + bn + c4 * 4] = v;
    }
}

// ---------------------------------------------------------------------------
// Fused attention middle (factorized softmax), fp32 exact. Unchanged from R1.
// ---------------------------------------------------------------------------
#define LT 8
#define NK 200
#define KT 32
#define NKT (HD / KT)

__global__ __launch_bounds__(256) void attn_kernel(
    const float* __restrict__ gq, const float* __restrict__ gkey,
    float* __restrict__ gctx)
{
    const int b  = blockIdx.y;
    const int l0 = blockIdx.x * LT;
    const int tid = threadIdx.x;
    const int lane = tid & 31;
    const int wid  = tid >> 5;

    __shared__ float sm_k[NK][KT + 1];
    __shared__ float sm_qs[LT][KT];
    __shared__ float sm_sc[LT][NK];
    __shared__ float sm_w[LT][NK];

    const float* keyS = gkey + (long)(b * SS) * HD;
    const float* keyT = gkey + (long)(BB * SS + b * TT) * HD;

    float acc[LT];
#pragma unroll
    for (int l = 0; l < LT; l++) acc[l] = 0.f;

    for (int kt = 0; kt < NKT; kt++) {
        {
            int l = tid >> 5, c = tid & 31;
            sm_qs[l][c] = gq[(long)(b * LL + l0 + l) * HD + kt * KT + c];
        }
        for (int i = tid; i < NK * KT; i += 256) {
            int r = i >> 5, c = i & 31;
            const float* srcp = (r < SS) ? (keyS + (long)r * HD)
                                         : (keyT + (long)(r - SS) * HD);
            sm_k[r][c] = srcp[kt * KT + c];
        }
        __syncthreads();

        if (tid < NK) {
#pragma unroll 8
            for (int k = 0; k < KT; k++) {
                float kv = sm_k[tid][k];
#pragma unroll
                for (int l = 0; l < LT; l++) acc[l] = fmaf(kv, sm_qs[l][k], acc[l]);
            }
        }
        __syncthreads();
    }

    if (tid < NK) {
#pragma unroll
        for (int l = 0; l < LT; l++) sm_sc[l][tid] = acc[l];
    }
    __syncthreads();

    {
        const int l = wid;
        const float sc1 = 1.0f / 32.0f;
        const float rs2 = 0.70710678118654752f;

        float vb[4], m = -1e30f;
#pragma unroll
        for (int ii = 0; ii < 4; ii++) {
            int j = lane + 32 * ii;
            vb[ii] = (j < SS) ? sm_sc[l][j] * sc1 : -1e30f;
            m = fmaxf(m, vb[ii]);
        }
#pragma unroll
        for (int off = 16; off; off >>= 1) m = fmaxf(m, __shfl_xor_sync(0xffffffffu, m, off));
        float sum = 0.f;
#pragma unroll
        for (int ii = 0; ii < 4; ii++) {
            int j = lane + 32 * ii;
            if (j < SS) { float e = __expf(vb[ii] - m); sm_w[l][j] = e; sum += e; }
        }
#pragma unroll
        for (int off = 16; off; off >>= 1) sum += __shfl_xor_sync(0xffffffffu, sum, off);
        float inv = rs2 / sum;
#pragma unroll
        for (int ii = 0; ii < 4; ii++) {
            int j = lane + 32 * ii;
            if (j < SS) sm_w[l][j] *= inv;
        }

        m = -1e30f;
#pragma unroll
        for (int ii = 0; ii < 4; ii++) {
            int j = lane + 32 * ii;
            vb[ii] = (j < TT) ? -sm_sc[l][SS + j] * sc1 : -1e30f;
            m = fmaxf(m, vb[ii]);
        }
#pragma unroll
        for (int off = 16; off; off >>= 1) m = fmaxf(m, __shfl_xor_sync(0xffffffffu, m, off));
        sum = 0.f;
#pragma unroll
        for (int ii = 0; ii < 4; ii++) {
            int j = lane + 32 * ii;
            if (j < TT) { float e = __expf(vb[ii] - m); sm_w[l][SS + j] = e; sum += e; }
        }
#pragma unroll
        for (int off = 16; off; off >>= 1) sum += __shfl_xor_sync(0xffffffffu, sum, off);
        inv = -rs2 / sum;
#pragma unroll
        for (int ii = 0; ii < 4; ii++) {
            int j = lane + 32 * ii;
            if (j < TT) sm_w[l][SS + j] *= inv;
        }
    }
    __syncthreads();

    for (int kt = 0; kt < NKT; kt++) {
        for (int i = tid; i < NK * KT; i += 256) {
            int r = i >> 5, c = i & 31;
            const float* srcp = (r < SS) ? (keyS + (long)r * HD)
                                         : (keyT + (long)(r - SS) * HD);
            sm_k[r][c] = srcp[kt * KT + c];
        }
        __syncthreads();

        const int l = wid;
        float a0 = 0.f;
#pragma unroll 8
        for (int j = 0; j < NK; j++) a0 = fmaf(sm_w[l][j], sm_k[j][lane], a0);
        gctx[(long)(b * LL + l0 + l) * HD + kt * KT + lane] = a0;
        __syncthreads();
    }
}

// ---------------------------------------------------------------------------
extern "C" void kernel_launch(void* const* d_in, const int* in_sizes, int n_in,
                              void* d_out, int out_size)
{
    const float* query = (const float*)d_in[0];
    const float* src   = (const float*)d_in[1];
    const float* trg   = (const float*)d_in[2];
    const float* Wq    = (const float*)d_in[3];
    const float* bq    = (const float*)d_in[4];
    const float* Ws    = (const float*)d_in[5];
    const float* bs    = (const float*)d_in[6];
    const float* Wo    = (const float*)d_in[7];
    const float* bo    = (const float*)d_in[8];
    float* out = (float*)d_out;

    float *qbuf, *keybuf, *ctxbuf;
    cudaGetSymbolAddress((void**)&qbuf,   g_q);
    cudaGetSymbolAddress((void**)&keybuf, g_key);
    cudaGetSymbolAddress((void**)&ctxbuf, g_ctx);

    // q-proj (M=1024,K=512) + key-proj (M=1600,K=2048, row-split src|trg) fused
    GemmDesc d1 = { query, query, 1 << 30, 0, Wq, bq, qbuf,   HD, QD, HD / 64 };
    GemmDesc d2 = { src,   trg,   BB * SS, 0, Ws, bs, keybuf, HD, FD, HD / 64 };
    int t1 = (BB * LL / 64) * (HD / 64);              // 128
    int t2 = (BB * (SS + TT) / 64) * (HD / 64);       // 200
    gemm_tc<<<t1 + t2, 128>>>(d1, d2, t1);

    // attention middle (factorized softmax) -> ctx
    attn_kernel<<<dim3(LL / LT, BB), 256>>>(qbuf, keybuf, ctxbuf);

    // out-proj: [query | ctx] @ Wo + bo  (M=1024, K=1024, col-split at 512)
    GemmDesc d3 = { query, ctxbuf, 1 << 30, QD, Wo, bo, out, OD, QD + HD, OD / 64 };
    int t3 = (BB * LL / 64) * (OD / 64);              // 128
    gemm_tc<<<t3, 128>>>(d3, d3, t3);
}

// round 4
// speedup vs baseline: 1.7393x; 1.2650x over previous
#include <cuda_runtime.h>
#include <cstdint>
#include <math.h>

// Problem constants
#define BB   8
#define LL   128
#define SS   100
#define TT   100
#define QD   512
#define FD   2048
#define HD   512
#define OD   512

#define MPAD_KEY 1664

// Scratch (device globals; no allocation APIs allowed)
__device__ float g_q[BB * LL * HD];
__device__ float g_key[MPAD_KEY * HD];
__device__ float g_ctx[BB * LL * HD];
__device__ float g_wqT[HD * QD];
__device__ float g_wsT[HD * FD];
__device__ float g_woT[OD * (QD + HD)];

// ---------------------------------------------------------------------------
__device__ __forceinline__ uint32_t s2u(const void* p) {
    uint32_t a;
    asm("{ .reg .u64 t; cvta.to.shared.u64 t, %1; cvt.u32.u64 %0, t; }" : "=r"(a) : "l"(p));
    return a;
}
__device__ __forceinline__ void cp16(uint32_t dst, const void* src) {
    asm volatile("cp.async.cg.shared.global [%0], [%1], 16;" :: "r"(dst), "l"(src));
}
#define CP_COMMIT() asm volatile("cp.async.commit_group;" ::: "memory")
#define CP_WAIT0()  asm volatile("cp.async.wait_group 0;" ::: "memory")

#define LDSM4(r, a) \
    asm volatile("ldmatrix.sync.aligned.m8n8.x4.shared.b16 {%0,%1,%2,%3}, [%4];" \
        : "=r"((r)[0]), "=r"((r)[1]), "=r"((r)[2]), "=r"((r)[3]) : "r"(a))

#define MMA_TF32(d, a, b0, b1) \
    asm volatile("mma.sync.aligned.m16n8k8.row.col.f32.tf32.tf32.f32 " \
        "{%0,%1,%2,%3}, {%4,%5,%6,%7}, {%8,%9}, {%0,%1,%2,%3};" \
        : "+f"((d)[0]), "+f"((d)[1]), "+f"((d)[2]), "+f"((d)[3]) \
        : "r"((a)[0]), "r"((a)[1]), "r"((a)[2]), "r"((a)[3]), "r"(b0), "r"(b1))

// ---------------------------------------------------------------------------
// Weight transpose + tf32 RN rounding:  WT[n][k] = rn_tf32(W[k][n]),  N = 512
// ---------------------------------------------------------------------------
__global__ __launch_bounds__(256) void transposeW(const float* __restrict__ W,
                                                  float* __restrict__ WT, int K, int N) {
    __shared__ float t[32][33];
    int k0 = blockIdx.x * 32, n0 = blockIdx.y * 32;
    int x = threadIdx.x & 31, y = threadIdx.x >> 5;
#pragma unroll
    for (int i = 0; i < 32; i += 8)
        t[y + i][x] = W[(long)(k0 + y + i) * N + n0 + x];
    __syncthreads();
#pragma unroll
    for (int i = 0; i < 32; i += 8) {
        float v = t[x][y + i];
        asm("cvt.rna.tf32.f32 %0, %0;" : "+f"(v));
        WT[(long)(n0 + y + i) * K + k0 + x] = v;
    }
}

// ---------------------------------------------------------------------------
// tf32 mma.sync GEMM: C[M,512] = A @ WT^T + bias
//   CTA tile 128x64, BK=32, 8 warps (4m x 2n), warp tile 32x32.
//   smem: A[2][128][32] swizzled, B[2][64][32] swizzled (n-major). 48KB dyn.
// ---------------------------------------------------------------------------
struct GD {
    const float* A0; const float* A1;
    int rowSplit;
    int colSplit;
    const float* WT;    // [512][K] n-major, tf32-rounded
    const float* bias;
    float* C;
    int K;
    int Mreal;
    int tilesM;
};

#define ABYTES 16384u
#define BBYTES 8192u
#define ABASE(b) ((b) * ABYTES)
#define BBASE(b) (2u * ABYTES + (b) * BBYTES)
#define DSMEM (2 * (ABYTES + BBYTES))      // 49152

extern __shared__ __align__(128) float dynsm[];

__global__ __launch_bounds__(256) void gemm_mma(GD ga, GD gb, int tilesA)
{
    const bool first = (blockIdx.x < (unsigned)tilesA);
    GD g = first ? ga : gb;
    const int lbid = first ? blockIdx.x : blockIdx.x - tilesA;

    const int bm = (lbid >> 3) * 128;      // tilesN = 512/64 = 8
    const int bn = (lbid & 7) * 64;
    const int tid  = threadIdx.x;
    const int lane = tid & 31;
    const int wid  = tid >> 5;
    const int wm   = (wid & 3) * 32;       // warp row base in tile
    const int wn   = (wid >> 2) * 32;      // warp col base in tile
    const int T = g.K >> 5;
    const int Mlast = g.Mreal - 1;

    const uint32_t smem = s2u(dynsm);

    // ldmatrix per-lane geometry
    const int lr     = lane & 7;            // row within 8-row tile
    const int rowoff = ((lane >> 3) & 1) * 8;
    const int coff   = lane >> 4;           // chunk offset (0/1)
    const int arow   = wm + rowoff + lr;    // + mi*16
    const int brow   = wn + rowoff + lr;    // + ng*16

    float acc[2][4][4];
#pragma unroll
    for (int mi = 0; mi < 2; mi++)
#pragma unroll
        for (int ni = 0; ni < 4; ni++)
#pragma unroll
            for (int j = 0; j < 4; j++) acc[mi][ni][j] = 0.f;

    // ---- tile loader ----
    auto issue_tile = [&](int t, int b) {
        const int k0 = t << 5;
        // A: 128 rows x 8 chunks = 1024, 4 per thread
#pragma unroll
        for (int i = 0; i < 4; i++) {
            int idx = tid + (i << 8);
            int r = idx >> 3, c = idx & 7;
            uint32_t dst = smem + ABASE(b) + (uint32_t)((r << 3) + (c ^ (r & 7))) * 16u;
            int gr = bm + r; if (gr > Mlast) gr = Mlast;
            int gc = k0 + c * 4;
            const float* p;
            if (g.colSplit) {
                p = (gc < g.colSplit) ? g.A0 + (long)gr * g.colSplit + gc
                                      : g.A1 + (long)gr * (g.K - g.colSplit) + (gc - g.colSplit);
            } else {
                p = (gr < g.rowSplit) ? g.A0 + (long)gr * g.K + gc
                                      : g.A1 + (long)(gr - g.rowSplit) * g.K + gc;
            }
            cp16(dst, p);
        }
        // B: 64 n-rows x 8 chunks = 512, 2 per thread
#pragma unroll
        for (int i = 0; i < 2; i++) {
            int idx = tid + (i << 8);
            int r = idx >> 3, c = idx & 7;
            uint32_t dst = smem + BBASE(b) + (uint32_t)((r << 3) + (c ^ (r & 7))) * 16u;
            cp16(dst, g.WT + (long)(bn + r) * g.K + k0 + c * 4);
        }
    };

    issue_tile(0, 0);
    CP_COMMIT();

    for (int t = 0; t < T; t++) {
        CP_WAIT0();
        __syncthreads();
        if (t + 1 < T) { issue_tile(t + 1, (t + 1) & 1); CP_COMMIT(); }

        const uint32_t ab = smem + ABASE(t & 1);
        const uint32_t bb = smem + BBASE(t & 1);
#pragma unroll
        for (int ks = 0; ks < 4; ks++) {
            uint32_t a[2][4], bf[2][4];
#pragma unroll
            for (int mi = 0; mi < 2; mi++) {
                uint32_t ad = ab + (uint32_t)(arow + mi * 16) * 128u
                                 + (uint32_t)(((ks << 1) + coff) ^ lr) * 16u;
                LDSM4(a[mi], ad);
            }
#pragma unroll
            for (int ng = 0; ng < 2; ng++) {
                uint32_t bd = bb + (uint32_t)(brow + ng * 16) * 128u
                                 + (uint32_t)(((ks << 1) + coff) ^ lr) * 16u;
                LDSM4(bf[ng], bd);
            }
            // RN-round A fragments to tf32 (weights pre-rounded)
#pragma unroll
            for (int mi = 0; mi < 2; mi++)
#pragma unroll
                for (int j = 0; j < 4; j++)
                    asm("cvt.rna.tf32.f32 %0, %0;" : "+r"(a[mi][j]));
#pragma unroll
            for (int mi = 0; mi < 2; mi++)
#pragma unroll
                for (int ni = 0; ni < 4; ni++) {
                    int ng = ni >> 1, sel = ni & 1;
                    MMA_TF32(acc[mi][ni], a[mi], bf[ng][sel], bf[ng][sel + 2]);
                }
        }
    }

    // ---- epilogue: direct stores with fused bias ----
    const int r0 = bm + wm + (lane >> 2);
    const int cb = bn + wn + 2 * (lane & 3);
#pragma unroll
    for (int ni = 0; ni < 4; ni++) {
        int col = cb + ni * 8;
        float2 bv = *(const float2*)&g.bias[col];
#pragma unroll
        for (int mi = 0; mi < 2; mi++) {
            int r = r0 + mi * 16;
            if (r < g.Mreal) {
                float2 v0 = { acc[mi][ni][0] + bv.x, acc[mi][ni][1] + bv.y };
                *(float2*)&g.C[(long)r * 512 + col] = v0;
            }
            if (r + 8 < g.Mreal) {
                float2 v1 = { acc[mi][ni][2] + bv.x, acc[mi][ni][3] + bv.y };
                *(float2*)&g.C[(long)(r + 8) * 512 + col] = v1;
            }
        }
    }
}

// ---------------------------------------------------------------------------
// Fused attention middle (factorized softmax), fp32 exact.
// ---------------------------------------------------------------------------
#define LT 8
#define NK 200
#define KT 32
#define NKT (HD / KT)

__global__ __launch_bounds__(256) void attn_kernel(
    const float* __restrict__ gq, const float* __restrict__ gkey,
    float* __restrict__ gctx)
{
    const int b  = blockIdx.y;
    const int l0 = blockIdx.x * LT;
    const int tid = threadIdx.x;
    const int lane = tid & 31;
    const int wid  = tid >> 5;

    __shared__ float sm_k[NK][KT + 1];
    __shared__ float sm_qs[LT][KT];
    __shared__ float sm_sc[LT][NK];
    __shared__ float sm_w[LT][NK];

    const float* keyS = gkey + (long)(b * SS) * HD;
    const float* keyT = gkey + (long)(BB * SS + b * TT) * HD;

    float acc[LT];
#pragma unroll
    for (int l = 0; l < LT; l++) acc[l] = 0.f;

    for (int kt = 0; kt < NKT; kt++) {
        {
            int l = tid >> 5, c = tid & 31;
            sm_qs[l][c] = gq[(long)(b * LL + l0 + l) * HD + kt * KT + c];
        }
        for (int i = tid; i < NK * KT; i += 256) {
            int r = i >> 5, c = i & 31;
            const float* srcp = (r < SS) ? (keyS + (long)r * HD)
                                         : (keyT + (long)(r - SS) * HD);
            sm_k[r][c] = srcp[kt * KT + c];
        }
        __syncthreads();

        if (tid < NK) {
#pragma unroll 8
            for (int k = 0; k < KT; k++) {
                float kv = sm_k[tid][k];
#pragma unroll
                for (int l = 0; l < LT; l++) acc[l] = fmaf(kv, sm_qs[l][k], acc[l]);
            }
        }
        __syncthreads();
    }

    if (tid < NK) {
#pragma unroll
        for (int l = 0; l < LT; l++) sm_sc[l][tid] = acc[l];
    }
    __syncthreads();

    {
        const int l = wid;
        const float sc1 = 1.0f / 32.0f;
        const float rs2 = 0.70710678118654752f;

        float vb[4], m = -1e30f;
#pragma unroll
        for (int ii = 0; ii < 4; ii++) {
            int j = lane + 32 * ii;
            vb[ii] = (j < SS) ? sm_sc[l][j] * sc1 : -1e30f;
            m = fmaxf(m, vb[ii]);
        }
#pragma unroll
        for (int off = 16; off; off >>= 1) m = fmaxf(m, __shfl_xor_sync(0xffffffffu, m, off));
        float sum = 0.f;
#pragma unroll
        for (int ii = 0; ii < 4; ii++) {
            int j = lane + 32 * ii;
            if (j < SS) { float e = __expf(vb[ii] - m); sm_w[l][j] = e; sum += e; }
        }
#pragma unroll
        for (int off = 16; off; off >>= 1) sum += __shfl_xor_sync(0xffffffffu, sum, off);
        float inv = rs2 / sum;
#pragma unroll
        for (int ii = 0; ii < 4; ii++) {
            int j = lane + 32 * ii;
            if (j < SS) sm_w[l][j] *= inv;
        }

        m = -1e30f;
#pragma unroll
        for (int ii = 0; ii < 4; ii++) {
            int j = lane + 32 * ii;
            vb[ii] = (j < TT) ? -sm_sc[l][SS + j] * sc1 : -1e30f;
            m = fmaxf(m, vb[ii]);
        }
#pragma unroll
        for (int off = 16; off; off >>= 1) m = fmaxf(m, __shfl_xor_sync(0xffffffffu, m, off));
        sum = 0.f;
#pragma unroll
        for (int ii = 0; ii < 4; ii++) {
            int j = lane + 32 * ii;
            if (j < TT) { float e = __expf(vb[ii] - m); sm_w[l][SS + j] = e; sum += e; }
        }
#pragma unroll
        for (int off = 16; off; off >>= 1) sum += __shfl_xor_sync(0xffffffffu, sum, off);
        inv = -rs2 / sum;
#pragma unroll
        for (int ii = 0; ii < 4; ii++) {
            int j = lane + 32 * ii;
            if (j < TT) sm_w[l][SS + j] *= inv;
        }
    }
    __syncthreads();

    for (int kt = 0; kt < NKT; kt++) {
        for (int i = tid; i < NK * KT; i += 256) {
            int r = i >> 5, c = i & 31;
            const float* srcp = (r < SS) ? (keyS + (long)r * HD)
                                         : (keyT + (long)(r - SS) * HD);
            sm_k[r][c] = srcp[kt * KT + c];
        }
        __syncthreads();

        const int l = wid;
        float a0 = 0.f;
#pragma unroll 8
        for (int j = 0; j < NK; j++) a0 = fmaf(sm_w[l][j], sm_k[j][lane], a0);
        gctx[(long)(b * LL + l0 + l) * HD + kt * KT + lane] = a0;
        __syncthreads();
    }
}

// ---------------------------------------------------------------------------
extern "C" void kernel_launch(void* const* d_in, const int* in_sizes, int n_in,
                              void* d_out, int out_size)
{
    const float* query = (const float*)d_in[0];
    const float* src   = (const float*)d_in[1];
    const float* trg   = (const float*)d_in[2];
    const float* Wq    = (const float*)d_in[3];
    const float* bq    = (const float*)d_in[4];
    const float* Ws    = (const float*)d_in[5];
    const float* bs    = (const float*)d_in[6];
    const float* Wo    = (const float*)d_in[7];
    const float* bo    = (const float*)d_in[8];
    float* out = (float*)d_out;

    float *qbuf, *keybuf, *ctxbuf, *wqT, *wsT, *woT;
    cudaGetSymbolAddress((void**)&qbuf,   g_q);
    cudaGetSymbolAddress((void**)&keybuf, g_key);
    cudaGetSymbolAddress((void**)&ctxbuf, g_ctx);
    cudaGetSymbolAddress((void**)&wqT,    g_wqT);
    cudaGetSymbolAddress((void**)&wsT,    g_wsT);
    cudaGetSymbolAddress((void**)&woT,    g_woT);

    cudaFuncSetAttribute(gemm_mma, cudaFuncAttributeMaxDynamicSharedMemorySize, DSMEM);

    // Weight transposes with tf32 RN rounding
    transposeW<<<dim3(QD / 32, HD / 32), 256>>>(Wq, wqT, QD, HD);
    transposeW<<<dim3(FD / 32, HD / 32), 256>>>(Ws, wsT, FD, HD);
    transposeW<<<dim3((QD + HD) / 32, HD / 32), 256>>>(Wo, woT, QD + HD, HD);

    // Fused q-proj + key-proj
    GD d1 = { query, query, 1 << 30, 0, wqT, bq, qbuf,   QD, BB * LL, 8 };
    GD d2 = { src,   trg,   BB * SS, 0, wsT, bs, keybuf, FD, MPAD_KEY / 128, 13 };
    d2.Mreal = BB * (SS + TT);
    int t1 = 8 * 8;       // 64
    int t2 = 13 * 8;      // 104
    gemm_mma<<<t1 + t2, 256, DSMEM>>>(d1, d2, t1);

    // Attention middle (factorized softmax)
    attn_kernel<<<dim3(LL / LT, BB), 256>>>(qbuf, keybuf, ctxbuf);

    // Out-proj: [query | ctx] @ Wo + bo
    GD d3 = { query, ctxbuf, 1 << 30, QD, woT, bo, out, QD + HD, BB * LL, 8 };
    gemm_mma<<<8 * 8, 256, DSMEM>>>(d3, d3, 8 * 8);
}

// round 5
// speedup vs baseline: 3.0447x; 1.7505x over previous
#include <cuda_runtime.h>
#include <cstdint>
#include <math.h>

// Problem constants
#define BB   8
#define LL   128
#define SS   100
#define TT   100
#define QD   512
#define FD   2048
#define HD   512
#define OD   512

#define MPAD_KEY 1664

// Scratch (device globals; no allocation APIs allowed)
__device__ float g_q[BB * LL * HD];
__device__ float g_key[MPAD_KEY * HD];
__device__ float g_ctx[BB * LL * HD];
__device__ float g_wqT[HD * QD];
__device__ float g_wsT[HD * FD];
__device__ float g_woT[OD * (QD + HD)];

// ---------------------------------------------------------------------------
__device__ __forceinline__ uint32_t s2u(const void* p) {
    uint32_t a;
    asm("{ .reg .u64 t; cvta.to.shared.u64 t, %1; cvt.u32.u64 %0, t; }" : "=r"(a) : "l"(p));
    return a;
}
__device__ __forceinline__ void cp16(uint32_t dst, const void* src) {
    asm volatile("cp.async.cg.shared.global [%0], [%1], 16;" :: "r"(dst), "l"(src));
}
#define CP_COMMIT()  asm volatile("cp.async.commit_group;" ::: "memory")
#define CP_WAITG(n)  asm volatile("cp.async.wait_group %0;" :: "n"(n) : "memory")

#define LDSM4(r, a) \
    asm volatile("ldmatrix.sync.aligned.m8n8.x4.shared.b16 {%0,%1,%2,%3}, [%4];" \
        : "=r"((r)[0]), "=r"((r)[1]), "=r"((r)[2]), "=r"((r)[3]) : "r"(a))

#define MMA_TF32(d, a, b0, b1) \
    asm volatile("mma.sync.aligned.m16n8k8.row.col.f32.tf32.tf32.f32 " \
        "{%0,%1,%2,%3}, {%4,%5,%6,%7}, {%8,%9}, {%0,%1,%2,%3};" \
        : "+f"((d)[0]), "+f"((d)[1]), "+f"((d)[2]), "+f"((d)[3]) \
        : "r"((a)[0]), "r"((a)[1]), "r"((a)[2]), "r"((a)[3]), "r"(b0), "r"(b1))

// ---------------------------------------------------------------------------
// Fused weight transposes + tf32 RN rounding (one launch, 3 segments), N = 512
// ---------------------------------------------------------------------------
__global__ __launch_bounds__(256) void transposeAll(
    const float* __restrict__ Wq, float* __restrict__ wqT,
    const float* __restrict__ Ws, float* __restrict__ wsT,
    const float* __restrict__ Wo, float* __restrict__ woT)
{
    __shared__ float t[32][33];
    int bid = blockIdx.x;
    const float* W; float* WT; int K;
    if (bid < 256)       { W = Wq; WT = wqT; K = 512;  }
    else if (bid < 1280) { W = Ws; WT = wsT; K = 2048; bid -= 256;  }
    else                 { W = Wo; WT = woT; K = 1024; bid -= 1280; }
    int k0 = (bid >> 4) * 32, n0 = (bid & 15) * 32;
    int x = threadIdx.x & 31, y = threadIdx.x >> 5;
#pragma unroll
    for (int i = 0; i < 32; i += 8)
        t[y + i][x] = W[(long)(k0 + y + i) * 512 + n0 + x];
    __syncthreads();
#pragma unroll
    for (int i = 0; i < 32; i += 8) {
        float v = t[x][y + i];
        asm("cvt.rna.tf32.f32 %0, %0;" : "+f"(v));
        WT[(long)(n0 + y + i) * K + k0 + x] = v;
    }
}

// ---------------------------------------------------------------------------
// tf32 mma.sync GEMM: C[M,512] = A @ WT^T + bias
//   CTA tile 64x64, BK=32, 128 threads (4 warps, 32x32 warp tiles),
//   4-stage cp.async pipeline (wait_group 2), 64KB dynamic smem.
// ---------------------------------------------------------------------------
struct GD {
    const float* A0; const float* A1;
    int rowSplit;
    int colSplit;
    const float* WT;
    const float* bias;
    float* C;
    int K;
    int Mreal;
    int tilesM;
};

#define STG_BYTES 16384u
#define ABASE(s) ((s) * STG_BYTES)
#define BBASE(s) ((s) * STG_BYTES + 8192u)
#define DSMEM    65536

extern __shared__ __align__(128) float dynsm[];

__global__ __launch_bounds__(128) void gemm_mma(GD ga, GD gb, int tilesA)
{
    const bool first = (blockIdx.x < (unsigned)tilesA);
    GD g = first ? ga : gb;
    const int lbid = first ? blockIdx.x : blockIdx.x - tilesA;

    const int bm = (lbid >> 3) * 64;       // tilesN = 8
    const int bn = (lbid & 7) * 64;
    const int tid  = threadIdx.x;
    const int lane = tid & 31;
    const int wid  = tid >> 5;
    const int wm   = (wid & 1) * 32;
    const int wn   = (wid >> 1) * 32;
    const int T = g.K >> 5;
    const int Mlast = g.Mreal - 1;

    const uint32_t smem = s2u(dynsm);

    const int lr     = lane & 7;
    const int rowoff = ((lane >> 3) & 1) * 8;
    const int coff   = lane >> 4;
    const int arow   = wm + rowoff + lr;
    const int brow   = wn + rowoff + lr;

    float acc[2][4][4];
#pragma unroll
    for (int mi = 0; mi < 2; mi++)
#pragma unroll
        for (int ni = 0; ni < 4; ni++)
#pragma unroll
            for (int j = 0; j < 4; j++) acc[mi][ni][j] = 0.f;

    auto issue_tile = [&](int t, int s) {
        const int k0 = t << 5;
        // A: 64 rows x 8 chunks = 512, 4 per thread
#pragma unroll
        for (int i = 0; i < 4; i++) {
            int idx = tid + (i << 7);
            int r = idx >> 3, c = idx & 7;
            uint32_t dst = smem + ABASE(s) + (uint32_t)((r << 3) + (c ^ (r & 7))) * 16u;
            int gr = bm + r; if (gr > Mlast) gr = Mlast;
            int gc = k0 + c * 4;
            const float* p;
            if (g.colSplit) {
                p = (gc < g.colSplit) ? g.A0 + (long)gr * g.colSplit + gc
                                      : g.A1 + (long)gr * (g.K - g.colSplit) + (gc - g.colSplit);
            } else {
                p = (gr < g.rowSplit) ? g.A0 + (long)gr * g.K + gc
                                      : g.A1 + (long)(gr - g.rowSplit) * g.K + gc;
            }
            cp16(dst, p);
        }
        // B: 64 n-rows x 8 chunks = 512, 4 per thread
#pragma unroll
        for (int i = 0; i < 4; i++) {
            int idx = tid + (i << 7);
            int r = idx >> 3, c = idx & 7;
            uint32_t dst = smem + BBASE(s) + (uint32_t)((r << 3) + (c ^ (r & 7))) * 16u;
            cp16(dst, g.WT + (long)(bn + r) * g.K + k0 + c * 4);
        }
    };

    // prologue: 3 stages in flight
    issue_tile(0, 0); CP_COMMIT();
    issue_tile(1, 1); CP_COMMIT();
    issue_tile(2, 2); CP_COMMIT();

    for (int t = 0; t < T; t++) {
        CP_WAITG(2);                 // tile t resident
        __syncthreads();             // stage (t-1)%4 free for reuse
        if (t + 3 < T) issue_tile(t + 3, (t + 3) & 3);
        CP_COMMIT();                 // unconditional: keeps group-count invariant

        const uint32_t ab = smem + ABASE(t & 3);
        const uint32_t bb = smem + BBASE(t & 3);
#pragma unroll
        for (int ks = 0; ks < 4; ks++) {
            uint32_t a[2][4], bf[2][4];
#pragma unroll
            for (int mi = 0; mi < 2; mi++) {
                uint32_t ad = ab + (uint32_t)(arow + mi * 16) * 128u
                                 + (uint32_t)(((ks << 1) + coff) ^ lr) * 16u;
                LDSM4(a[mi], ad);
            }
#pragma unroll
            for (int ng = 0; ng < 2; ng++) {
                uint32_t bd = bb + (uint32_t)(brow + ng * 16) * 128u
                                 + (uint32_t)(((ks << 1) + coff) ^ lr) * 16u;
                LDSM4(bf[ng], bd);
            }
#pragma unroll
            for (int mi = 0; mi < 2; mi++)
#pragma unroll
                for (int j = 0; j < 4; j++)
                    asm("cvt.rna.tf32.f32 %0, %0;" : "+r"(a[mi][j]));
#pragma unroll
            for (int mi = 0; mi < 2; mi++)
#pragma unroll
                for (int ni = 0; ni < 4; ni++) {
                    int ng = ni >> 1, sel = ni & 1;
                    MMA_TF32(acc[mi][ni], a[mi], bf[ng][sel], bf[ng][sel + 2]);
                }
        }
    }

    // epilogue: direct stores with fused bias
    const int r0 = bm + wm + (lane >> 2);
    const int cb = bn + wn + 2 * (lane & 3);
#pragma unroll
    for (int ni = 0; ni < 4; ni++) {
        int col = cb + ni * 8;
        float2 bv = *(const float2*)&g.bias[col];
#pragma unroll
        for (int mi = 0; mi < 2; mi++) {
            int r = r0 + mi * 16;
            if (r < g.Mreal) {
                float2 v0 = { acc[mi][ni][0] + bv.x, acc[mi][ni][1] + bv.y };
                *(float2*)&g.C[(long)r * 512 + col] = v0;
            }
            if (r + 8 < g.Mreal) {
                float2 v1 = { acc[mi][ni][2] + bv.x, acc[mi][ni][3] + bv.y };
                *(float2*)&g.C[(long)(r + 8) * 512 + col] = v1;
            }
        }
    }
}

// ---------------------------------------------------------------------------
// Attention middle (factorized softmax), gmem-direct streaming, fp32.
//   CTA = (8 l's, batch b), 256 threads.
//   Phase 1: thread r in [0,200) dots its key row against 8 q rows (q in smem).
//   Phase 3: per-warp softmax; weights stored transposed [j][l] with signs.
//   Phase 4: outer product: coalesced float4 key loads x broadcast w-float4.
// ---------------------------------------------------------------------------
__global__ __launch_bounds__(256) void attn2(
    const float* __restrict__ gq, const float* __restrict__ gkey,
    float* __restrict__ gctx)
{
    const int b  = blockIdx.y;
    const int l0 = blockIdx.x * 8;
    const int tid = threadIdx.x;
    const int lane = tid & 31;
    const int wid  = tid >> 5;

    __shared__ __align__(16) float qsm[8 * 512];
    __shared__ __align__(16) float ssc[8 * 200];
    __shared__ __align__(16) float wts[200 * 8];

    const float* keyS = gkey + (long)(b * SS) * HD;
    const float* keyT = gkey + (long)(BB * SS + b * TT) * HD;

    // load q rows (8 x 512)
#pragma unroll
    for (int i = 0; i < 4; i++) {
        int idx = tid + (i << 8);
        int l = idx >> 7, c4 = idx & 127;
        ((float4*)qsm)[l * 128 + c4] =
            __ldg((const float4*)(gq + (long)(b * LL + l0 + l) * HD) + c4);
    }
    __syncthreads();

    // ---- phase 1: qs/qt dots ----
    if (tid < 200) {
        const float* kr = (tid < SS) ? keyS + (long)tid * HD
                                     : keyT + (long)(tid - SS) * HD;
        float acc[8];
#pragma unroll
        for (int l = 0; l < 8; l++) acc[l] = 0.f;
#pragma unroll 2
        for (int k4 = 0; k4 < 128; k4++) {
            float4 kv = __ldg((const float4*)kr + k4);
#pragma unroll
            for (int l = 0; l < 8; l++) {
                float4 qv = *(const float4*)&qsm[l * 512 + k4 * 4];
                acc[l] += kv.x * qv.x + kv.y * qv.y + kv.z * qv.z + kv.w * qv.w;
            }
        }
#pragma unroll
        for (int l = 0; l < 8; l++) ssc[l * 200 + tid] = acc[l];
    }
    __syncthreads();

    // ---- phase 3: factorized softmax (warp l = wid) ----
    {
        const int l = wid;
        const float sc1 = 1.0f / 32.0f;           // 1/sqrt(2*HD)
        const float rs2 = 0.70710678118654752f;   // 1/sqrt(2)

        float vb[4], m = -1e30f;
#pragma unroll
        for (int ii = 0; ii < 4; ii++) {
            int j = lane + 32 * ii;
            vb[ii] = (j < SS) ? ssc[l * 200 + j] * sc1 : -1e30f;
            m = fmaxf(m, vb[ii]);
        }
#pragma unroll
        for (int off = 16; off; off >>= 1) m = fmaxf(m, __shfl_xor_sync(0xffffffffu, m, off));
        float sum = 0.f;
#pragma unroll
        for (int ii = 0; ii < 4; ii++) {
            int j = lane + 32 * ii;
            if (j < SS) { vb[ii] = __expf(vb[ii] - m); sum += vb[ii]; }
        }
#pragma unroll
        for (int off = 16; off; off >>= 1) sum += __shfl_xor_sync(0xffffffffu, sum, off);
        float inv = rs2 / sum;
#pragma unroll
        for (int ii = 0; ii < 4; ii++) {
            int j = lane + 32 * ii;
            if (j < SS) wts[j * 8 + l] = vb[ii] * inv;
        }

        m = -1e30f;
#pragma unroll
        for (int ii = 0; ii < 4; ii++) {
            int j = lane + 32 * ii;
            vb[ii] = (j < TT) ? -ssc[l * 200 + SS + j] * sc1 : -1e30f;
            m = fmaxf(m, vb[ii]);
        }
#pragma unroll
        for (int off = 16; off; off >>= 1) m = fmaxf(m, __shfl_xor_sync(0xffffffffu, m, off));
        sum = 0.f;
#pragma unroll
        for (int ii = 0; ii < 4; ii++) {
            int j = lane + 32 * ii;
            if (j < TT) { vb[ii] = __expf(vb[ii] - m); sum += vb[ii]; }
        }
#pragma unroll
        for (int off = 16; off; off >>= 1) sum += __shfl_xor_sync(0xffffffffu, sum, off);
        inv = -rs2 / sum;                         // minus sign folded in
#pragma unroll
        for (int ii = 0; ii < 4; ii++) {
            int j = lane + 32 * ii;
            if (j < TT) wts[(SS + j) * 8 + l] = vb[ii] * inv;
        }
    }
    __syncthreads();

    // ---- phase 4: ctx = w @ keys (outer-product streaming) ----
    {
        const int grp = tid >> 7;        // 0: l 0-3, 1: l 4-7
        const int ci  = tid & 127;       // column/4
        const int lb  = grp * 4;
        float4 a0 = {0,0,0,0}, a1 = {0,0,0,0}, a2 = {0,0,0,0}, a3 = {0,0,0,0};

#pragma unroll 4
        for (int j = 0; j < SS; j++) {
            float4 kv = __ldg((const float4*)(keyS + (long)j * HD) + ci);
            float4 w4 = *(const float4*)&wts[j * 8 + lb];
            a0.x += w4.x * kv.x; a0.y += w4.x * kv.y; a0.z += w4.x * kv.z; a0.w += w4.x * kv.w;
            a1.x += w4.y * kv.x; a1.y += w4.y * kv.y; a1.z += w4.y * kv.z; a1.w += w4.y * kv.w;
            a2.x += w4.z * kv.x; a2.y += w4.z * kv.y; a2.z += w4.z * kv.z; a2.w += w4.z * kv.w;
            a3.x += w4.w * kv.x; a3.y += w4.w * kv.y; a3.z += w4.w * kv.z; a3.w += w4.w * kv.w;
        }
#pragma unroll 4
        for (int j = 0; j < TT; j++) {
            float4 kv = __ldg((const float4*)(keyT + (long)j * HD) + ci);
            float4 w4 = *(const float4*)&wts[(SS + j) * 8 + lb];
            a0.x += w4.x * kv.x; a0.y += w4.x * kv.y; a0.z += w4.x * kv.z; a0.w += w4.x * kv.w;
            a1.x += w4.y * kv.x; a1.y += w4.y * kv.y; a1.z += w4.y * kv.z; a1.w += w4.y * kv.w;
            a2.x += w4.z * kv.x; a2.y += w4.z * kv.y; a2.z += w4.z * kv.z; a2.w += w4.z * kv.w;
            a3.x += w4.w * kv.x; a3.y += w4.w * kv.y; a3.z += w4.w * kv.z; a3.w += w4.w * kv.w;
        }

        float* base = gctx + (long)(b * LL + l0 + lb) * HD + ci * 4;
        *(float4*)(base + 0 * HD) = a0;
        *(float4*)(base + 1 * HD) = a1;
        *(float4*)(base + 2 * HD) = a2;
        *(float4*)(base + 3 * HD) = a3;
    }
}

// ---------------------------------------------------------------------------
extern "C" void kernel_launch(void* const* d_in, const int* in_sizes, int n_in,
                              void* d_out, int out_size)
{
    const float* query = (const float*)d_in[0];
    const float* src   = (const float*)d_in[1];
    const float* trg   = (const float*)d_in[2];
    const float* Wq    = (const float*)d_in[3];
    const float* bq    = (const float*)d_in[4];
    const float* Ws    = (const float*)d_in[5];
    const float* bs    = (const float*)d_in[6];
    const float* Wo    = (const float*)d_in[7];
    const float* bo    = (const float*)d_in[8];
    float* out = (float*)d_out;

    float *qbuf, *keybuf, *ctxbuf, *wqT, *wsT, *woT;
    cudaGetSymbolAddress((void**)&qbuf,   g_q);
    cudaGetSymbolAddress((void**)&keybuf, g_key);
    cudaGetSymbolAddress((void**)&ctxbuf, g_ctx);
    cudaGetSymbolAddress((void**)&wqT,    g_wqT);
    cudaGetSymbolAddress((void**)&wsT,    g_wsT);
    cudaGetSymbolAddress((void**)&woT,    g_woT);

    cudaFuncSetAttribute(gemm_mma, cudaFuncAttributeMaxDynamicSharedMemorySize, DSMEM);

    // Fused weight transposes (tf32 RN pre-rounding)
    transposeAll<<<1792, 256>>>(Wq, wqT, Ws, wsT, Wo, woT);

    // Fused key-proj (first: long K) + q-proj
    GD dKey = { src,   trg,   BB * SS, 0, wsT, bs, keybuf, FD, BB * (SS + TT), 26 };
    GD dQ   = { query, query, 1 << 30, 0, wqT, bq, qbuf,   QD, BB * LL, 16 };
    int tKey = 26 * 8;    // 208
    int tQ   = 16 * 8;    // 128
    gemm_mma<<<tKey + tQ, 128, DSMEM>>>(dKey, dQ, tKey);

    // Attention middle (factorized softmax)
    attn2<<<dim3(LL / 8, BB), 256>>>(qbuf, keybuf, ctxbuf);

    // Out-proj: [query | ctx] @ Wo + bo
    GD dO = { query, ctxbuf, 1 << 30, QD, woT, bo, out, QD + HD, BB * LL, 16 };
    gemm_mma<<<16 * 8, 128, DSMEM>>>(dO, dO, 16 * 8);
}

// round 6
// speedup vs baseline: 3.0597x; 1.0050x over previous
#include <cuda_runtime.h>
#include <cstdint>
#include <math.h>

// Problem constants
#define BB   8
#define LL   128
#define SS   100
#define TT   100
#define QD   512
#define FD   2048
#define HD   512
#define OD   512

#define MPAD_KEY 1664

// Scratch (device globals; no allocation APIs allowed)
__device__ float g_q[BB * LL * HD];
__device__ float g_key[MPAD_KEY * HD];
__device__ float g_ctx[BB * LL * HD];
__device__ float g_wqT[HD * QD];
__device__ float g_wsT[HD * FD];
__device__ float g_woT[OD * (QD + HD)];

// ---------------------------------------------------------------------------
__device__ __forceinline__ uint32_t s2u(const void* p) {
    uint32_t a;
    asm("{ .reg .u64 t; cvta.to.shared.u64 t, %1; cvt.u32.u64 %0, t; }" : "=r"(a) : "l"(p));
    return a;
}
__device__ __forceinline__ void cp16(uint32_t dst, const void* src) {
    asm volatile("cp.async.cg.shared.global [%0], [%1], 16;" :: "r"(dst), "l"(src));
}
#define CP_COMMIT()  asm volatile("cp.async.commit_group;" ::: "memory")
#define CP_WAITG(n)  asm volatile("cp.async.wait_group %0;" :: "n"(n) : "memory")

#define LDSM4(r, a) \
    asm volatile("ldmatrix.sync.aligned.m8n8.x4.shared.b16 {%0,%1,%2,%3}, [%4];" \
        : "=r"((r)[0]), "=r"((r)[1]), "=r"((r)[2]), "=r"((r)[3]) : "r"(a))

#define MMA_TF32(d, a, b0, b1) \
    asm volatile("mma.sync.aligned.m16n8k8.row.col.f32.tf32.tf32.f32 " \
        "{%0,%1,%2,%3}, {%4,%5,%6,%7}, {%8,%9}, {%0,%1,%2,%3};" \
        : "+f"((d)[0]), "+f"((d)[1]), "+f"((d)[2]), "+f"((d)[3]) \
        : "r"((a)[0]), "r"((a)[1]), "r"((a)[2]), "r"((a)[3]), "r"(b0), "r"(b1))

// ---------------------------------------------------------------------------
// Fused weight transposes + tf32 RN rounding (one launch, 3 segments), N = 512
// ---------------------------------------------------------------------------
__global__ __launch_bounds__(256) void transposeAll(
    const float* __restrict__ Wq, float* __restrict__ wqT,
    const float* __restrict__ Ws, float* __restrict__ wsT,
    const float* __restrict__ Wo, float* __restrict__ woT)
{
    __shared__ float t[32][33];
    int bid = blockIdx.x;
    const float* W; float* WT; int K;
    if (bid < 256)       { W = Wq; WT = wqT; K = 512;  }
    else if (bid < 1280) { W = Ws; WT = wsT; K = 2048; bid -= 256;  }
    else                 { W = Wo; WT = woT; K = 1024; bid -= 1280; }
    int k0 = (bid >> 4) * 32, n0 = (bid & 15) * 32;
    int x = threadIdx.x & 31, y = threadIdx.x >> 5;
#pragma unroll
    for (int i = 0; i < 32; i += 8)
        t[y + i][x] = W[(long)(k0 + y + i) * 512 + n0 + x];
    __syncthreads();
#pragma unroll
    for (int i = 0; i < 32; i += 8) {
        float v = t[x][y + i];
        asm("cvt.rna.tf32.f32 %0, %0;" : "+f"(v));
        WT[(long)(n0 + y + i) * K + k0 + x] = v;
    }
}

// ---------------------------------------------------------------------------
// tf32 mma.sync GEMM: C[M,512] = A @ WT^T + bias
//   CTA tile 64x64, BK=32, 128 threads (4 warps, 32x32 warp tiles),
//   4-stage cp.async pipeline (wait_group 2), 64KB dynamic smem.
// ---------------------------------------------------------------------------
struct GD {
    const float* A0; const float* A1;
    int rowSplit;
    int colSplit;
    const float* WT;
    const float* bias;
    float* C;
    int K;
    int Mreal;
    int tilesM;
};

#define STG_BYTES 16384u
#define ABASE(s) ((s) * STG_BYTES)
#define BBASE(s) ((s) * STG_BYTES + 8192u)
#define DSMEM    65536

extern __shared__ __align__(128) float dynsm[];

__global__ __launch_bounds__(128) void gemm_mma(GD ga, GD gb, int tilesA)
{
    const bool first = (blockIdx.x < (unsigned)tilesA);
    GD g = first ? ga : gb;
    const int lbid = first ? blockIdx.x : blockIdx.x - tilesA;

    const int bm = (lbid >> 3) * 64;       // tilesN = 8
    const int bn = (lbid & 7) * 64;
    const int tid  = threadIdx.x;
    const int lane = tid & 31;
    const int wid  = tid >> 5;
    const int wm   = (wid & 1) * 32;
    const int wn   = (wid >> 1) * 32;
    const int T = g.K >> 5;
    const int Mlast = g.Mreal - 1;

    const uint32_t smem = s2u(dynsm);

    const int lr     = lane & 7;
    const int rowoff = ((lane >> 3) & 1) * 8;
    const int coff   = lane >> 4;
    const int arow   = wm + rowoff + lr;
    const int brow   = wn + rowoff + lr;

    float acc[2][4][4];
#pragma unroll
    for (int mi = 0; mi < 2; mi++)
#pragma unroll
        for (int ni = 0; ni < 4; ni++)
#pragma unroll
            for (int j = 0; j < 4; j++) acc[mi][ni][j] = 0.f;

    auto issue_tile = [&](int t, int s) {
        const int k0 = t << 5;
        // A: 64 rows x 8 chunks = 512, 4 per thread
#pragma unroll
        for (int i = 0; i < 4; i++) {
            int idx = tid + (i << 7);
            int r = idx >> 3, c = idx & 7;
            uint32_t dst = smem + ABASE(s) + (uint32_t)((r << 3) + (c ^ (r & 7))) * 16u;
            int gr = bm + r; if (gr > Mlast) gr = Mlast;
            int gc = k0 + c * 4;
            const float* p;
            if (g.colSplit) {
                p = (gc < g.colSplit) ? g.A0 + (long)gr * g.colSplit + gc
                                      : g.A1 + (long)gr * (g.K - g.colSplit) + (gc - g.colSplit);
            } else {
                p = (gr < g.rowSplit) ? g.A0 + (long)gr * g.K + gc
                                      : g.A1 + (long)(gr - g.rowSplit) * g.K + gc;
            }
            cp16(dst, p);
        }
        // B: 64 n-rows x 8 chunks = 512, 4 per thread
#pragma unroll
        for (int i = 0; i < 4; i++) {
            int idx = tid + (i << 7);
            int r = idx >> 3, c = idx & 7;
            uint32_t dst = smem + BBASE(s) + (uint32_t)((r << 3) + (c ^ (r & 7))) * 16u;
            cp16(dst, g.WT + (long)(bn + r) * g.K + k0 + c * 4);
        }
    };

    // prologue: 3 stages in flight
    issue_tile(0, 0); CP_COMMIT();
    issue_tile(1, 1); CP_COMMIT();
    issue_tile(2, 2); CP_COMMIT();

    for (int t = 0; t < T; t++) {
        CP_WAITG(2);                 // tile t resident
        __syncthreads();             // stage (t-1)%4 free for reuse
        if (t + 3 < T) issue_tile(t + 3, (t + 3) & 3);
        CP_COMMIT();                 // unconditional: keeps group-count invariant

        const uint32_t ab = smem + ABASE(t & 3);
        const uint32_t bb = smem + BBASE(t & 3);
#pragma unroll
        for (int ks = 0; ks < 4; ks++) {
            uint32_t a[2][4], bf[2][4];
#pragma unroll
            for (int mi = 0; mi < 2; mi++) {
                uint32_t ad = ab + (uint32_t)(arow + mi * 16) * 128u
                                 + (uint32_t)(((ks << 1) + coff) ^ lr) * 16u;
                LDSM4(a[mi], ad);
            }
#pragma unroll
            for (int ng = 0; ng < 2; ng++) {
                uint32_t bd = bb + (uint32_t)(brow + ng * 16) * 128u
                                 + (uint32_t)(((ks << 1) + coff) ^ lr) * 16u;
                LDSM4(bf[ng], bd);
            }
#pragma unroll
            for (int mi = 0; mi < 2; mi++)
#pragma unroll
                for (int j = 0; j < 4; j++)
                    asm("cvt.rna.tf32.f32 %0, %0;" : "+r"(a[mi][j]));
#pragma unroll
            for (int mi = 0; mi < 2; mi++)
#pragma unroll
                for (int ni = 0; ni < 4; ni++) {
                    int ng = ni >> 1, sel = ni & 1;
                    MMA_TF32(acc[mi][ni], a[mi], bf[ng][sel], bf[ng][sel + 2]);
                }
        }
    }

    // epilogue: direct stores with fused bias
    const int r0 = bm + wm + (lane >> 2);
    const int cb = bn + wn + 2 * (lane & 3);
#pragma unroll
    for (int ni = 0; ni < 4; ni++) {
        int col = cb + ni * 8;
        float2 bv = *(const float2*)&g.bias[col];
#pragma unroll
        for (int mi = 0; mi < 2; mi++) {
            int r = r0 + mi * 16;
            if (r < g.Mreal) {
                float2 v0 = { acc[mi][ni][0] + bv.x, acc[mi][ni][1] + bv.y };
                *(float2*)&g.C[(long)r * 512 + col] = v0;
            }
            if (r + 8 < g.Mreal) {
                float2 v1 = { acc[mi][ni][2] + bv.x, acc[mi][ni][3] + bv.y };
                *(float2*)&g.C[(long)(r + 8) * 512 + col] = v1;
            }
        }
    }
}

// ---------------------------------------------------------------------------
// Attention middle (factorized softmax), gmem-direct streaming, fp32.
//   CTA = (8 l's, batch b), 256 threads.
//   Phase 1: thread r in [0,200) dots its key row against 8 q rows (q in smem).
//   Phase 3: per-warp softmax; weights stored transposed [j][l] with signs.
//   Phase 4: outer product: coalesced float4 key loads x broadcast w-float4.
// ---------------------------------------------------------------------------
__global__ __launch_bounds__(256) void attn2(
    const float* __restrict__ gq, const float* __restrict__ gkey,
    float* __restrict__ gctx)
{
    const int b  = blockIdx.y;
    const int l0 = blockIdx.x * 8;
    const int tid = threadIdx.x;
    const int lane = tid & 31;
    const int wid  = tid >> 5;

    __shared__ __align__(16) float qsm[8 * 512];
    __shared__ __align__(16) float ssc[8 * 200];
    __shared__ __align__(16) float wts[200 * 8];

    const float* keyS = gkey + (long)(b * SS) * HD;
    const float* keyT = gkey + (long)(BB * SS + b * TT) * HD;

    // load q rows (8 x 512)
#pragma unroll
    for (int i = 0; i < 4; i++) {
        int idx = tid + (i << 8);
        int l = idx >> 7, c4 = idx & 127;
        ((float4*)qsm)[l * 128 + c4] =
            __ldg((const float4*)(gq + (long)(b * LL + l0 + l) * HD) + c4);
    }
    __syncthreads();

    // ---- phase 1: qs/qt dots ----
    if (tid < 200) {
        const float* kr = (tid < SS) ? keyS + (long)tid * HD
                                     : keyT + (long)(tid - SS) * HD;
        float acc[8];
#pragma unroll
        for (int l = 0; l < 8; l++) acc[l] = 0.f;
#pragma unroll 2
        for (int k4 = 0; k4 < 128; k4++) {
            float4 kv = __ldg((const float4*)kr + k4);
#pragma unroll
            for (int l = 0; l < 8; l++) {
                float4 qv = *(const float4*)&qsm[l * 512 + k4 * 4];
                acc[l] += kv.x * qv.x + kv.y * qv.y + kv.z * qv.z + kv.w * qv.w;
            }
        }
#pragma unroll
        for (int l = 0; l < 8; l++) ssc[l * 200 + tid] = acc[l];
    }
    __syncthreads();

    // ---- phase 3: factorized softmax (warp l = wid) ----
    {
        const int l = wid;
        const float sc1 = 1.0f / 32.0f;           // 1/sqrt(2*HD)
        const float rs2 = 0.70710678118654752f;   // 1/sqrt(2)

        float vb[4], m = -1e30f;
#pragma unroll
        for (int ii = 0; ii < 4; ii++) {
            int j = lane + 32 * ii;
            vb[ii] = (j < SS) ? ssc[l * 200 + j] * sc1 : -1e30f;
            m = fmaxf(m, vb[ii]);
        }
#pragma unroll
        for (int off = 16; off; off >>= 1) m = fmaxf(m, __shfl_xor_sync(0xffffffffu, m, off));
        float sum = 0.f;
#pragma unroll
        for (int ii = 0; ii < 4; ii++) {
            int j = lane + 32 * ii;
            if (j < SS) { vb[ii] = __expf(vb[ii] - m); sum += vb[ii]; }
        }
#pragma unroll
        for (int off = 16; off; off >>= 1) sum += __shfl_xor_sync(0xffffffffu, sum, off);
        float inv = rs2 / sum;
#pragma unroll
        for (int ii = 0; ii < 4; ii++) {
            int j = lane + 32 * ii;
            if (j < SS) wts[j * 8 + l] = vb[ii] * inv;
        }

        m = -1e30f;
#pragma unroll
        for (int ii = 0; ii < 4; ii++) {
            int j = lane + 32 * ii;
            vb[ii] = (j < TT) ? -ssc[l * 200 + SS + j] * sc1 : -1e30f;
            m = fmaxf(m, vb[ii]);
        }
#pragma unroll
        for (int off = 16; off; off >>= 1) m = fmaxf(m, __shfl_xor_sync(0xffffffffu, m, off));
        sum = 0.f;
#pragma unroll
        for (int ii = 0; ii < 4; ii++) {
            int j = lane + 32 * ii;
            if (j < TT) { vb[ii] = __expf(vb[ii] - m); sum += vb[ii]; }
        }
#pragma unroll
        for (int off = 16; off; off >>= 1) sum += __shfl_xor_sync(0xffffffffu, sum, off);
        inv = -rs2 / sum;                         // minus sign folded in
#pragma unroll
        for (int ii = 0; ii < 4; ii++) {
            int j = lane + 32 * ii;
            if (j < TT) wts[(SS + j) * 8 + l] = vb[ii] * inv;
        }
    }
    __syncthreads();

    // ---- phase 4: ctx = w @ keys (outer-product streaming) ----
    {
        const int grp = tid >> 7;        // 0: l 0-3, 1: l 4-7
        const int ci  = tid & 127;       // column/4
        const int lb  = grp * 4;
        float4 a0 = {0,0,0,0}, a1 = {0,0,0,0}, a2 = {0,0,0,0}, a3 = {0,0,0,0};

#pragma unroll 4
        for (int j = 0; j < SS; j++) {
            float4 kv = __ldg((const float4*)(keyS + (long)j * HD) + ci);
            float4 w4 = *(const float4*)&wts[j * 8 + lb];
            a0.x += w4.x * kv.x; a0.y += w4.x * kv.y; a0.z += w4.x * kv.z; a0.w += w4.x * kv.w;
            a1.x += w4.y * kv.x; a1.y += w4.y * kv.y; a1.z += w4.y * kv.z; a1.w += w4.y * kv.w;
            a2.x += w4.z * kv.x; a2.y += w4.z * kv.y; a2.z += w4.z * kv.z; a2.w += w4.z * kv.w;
            a3.x += w4.w * kv.x; a3.y += w4.w * kv.y; a3.z += w4.w * kv.z; a3.w += w4.w * kv.w;
        }
#pragma unroll 4
        for (int j = 0; j < TT; j++) {
            float4 kv = __ldg((const float4*)(keyT + (long)j * HD) + ci);
            float4 w4 = *(const float4*)&wts[(SS + j) * 8 + lb];
            a0.x += w4.x * kv.x; a0.y += w4.x * kv.y; a0.z += w4.x * kv.z; a0.w += w4.x * kv.w;
            a1.x += w4.y * kv.x; a1.y += w4.y * kv.y; a1.z += w4.y * kv.z; a1.w += w4.y * kv.w;
            a2.x += w4.z * kv.x; a2.y += w4.z * kv.y; a2.z += w4.z * kv.z; a2.w += w4.z * kv.w;
            a3.x += w4.w * kv.x; a3.y += w4.w * kv.y; a3.z += w4.w * kv.z; a3.w += w4.w * kv.w;
        }

        float* base = gctx + (long)(b * LL + l0 + lb) * HD + ci * 4;
        *(float4*)(base + 0 * HD) = a0;
        *(float4*)(base + 1 * HD) = a1;
        *(float4*)(base + 2 * HD) = a2;
        *(float4*)(base + 3 * HD) = a3;
    }
}

// ---------------------------------------------------------------------------
extern "C" void kernel_launch(void* const* d_in, const int* in_sizes, int n_in,
                              void* d_out, int out_size)
{
    const float* query = (const float*)d_in[0];
    const float* src   = (const float*)d_in[1];
    const float* trg   = (const float*)d_in[2];
    const float* Wq    = (const float*)d_in[3];
    const float* bq    = (const float*)d_in[4];
    const float* Ws    = (const float*)d_in[5];
    const float* bs    = (const float*)d_in[6];
    const float* Wo    = (const float*)d_in[7];
    const float* bo    = (const float*)d_in[8];
    float* out = (float*)d_out;

    float *qbuf, *keybuf, *ctxbuf, *wqT, *wsT, *woT;
    cudaGetSymbolAddress((void**)&qbuf,   g_q);
    cudaGetSymbolAddress((void**)&keybuf, g_key);
    cudaGetSymbolAddress((void**)&ctxbuf, g_ctx);
    cudaGetSymbolAddress((void**)&wqT,    g_wqT);
    cudaGetSymbolAddress((void**)&wsT,    g_wsT);
    cudaGetSymbolAddress((void**)&woT,    g_woT);

    cudaFuncSetAttribute(gemm_mma, cudaFuncAttributeMaxDynamicSharedMemorySize, DSMEM);

    // Fused weight transposes (tf32 RN pre-rounding)
    transposeAll<<<1792, 256>>>(Wq, wqT, Ws, wsT, Wo, woT);

    // Fused key-proj (first: long K) + q-proj
    GD dKey = { src,   trg,   BB * SS, 0, wsT, bs, keybuf, FD, BB * (SS + TT), 26 };
    GD dQ   = { query, query, 1 << 30, 0, wqT, bq, qbuf,   QD, BB * LL, 16 };
    int tKey = 26 * 8;    // 208
    int tQ   = 16 * 8;    // 128
    gemm_mma<<<tKey + tQ, 128, DSMEM>>>(dKey, dQ, tKey);

    // Attention middle (factorized softmax)
    attn2<<<dim3(LL / 8, BB), 256>>>(qbuf, keybuf, ctxbuf);

    // Out-proj: [query | ctx] @ Wo + bo
    GD dO = { query, ctxbuf, 1 << 30, QD, woT, bo, out, QD + HD, BB * LL, 16 };
    gemm_mma<<<16 * 8, 128, DSMEM>>>(dO, dO, 16 * 8);
}

// round 7
// speedup vs baseline: 3.4413x; 1.1247x over previous
#include <cuda_runtime.h>
#include <cstdint>
#include <math.h>

// Problem constants
#define BB   8
#define LL   128
#define SS   100
#define TT   100
#define QD   512
#define FD   2048
#define HD   512
#define OD   512

// Scratch (device globals; no allocation APIs allowed)
__device__ float g_q[BB * LL * HD];
__device__ float g_key[BB * (SS + TT) * HD];
__device__ float g_ctx[BB * LL * HD];
__device__ float g_wqT[HD * QD];
__device__ float g_wsT[HD * FD];
__device__ float g_woT[OD * (QD + HD)];

// ---------------------------------------------------------------------------
__device__ __forceinline__ uint32_t s2u(const void* p) {
    uint32_t a;
    asm("{ .reg .u64 t; cvta.to.shared.u64 t, %1; cvt.u32.u64 %0, t; }" : "=r"(a) : "l"(p));
    return a;
}
__device__ __forceinline__ void cp16(uint32_t dst, const void* src) {
    asm volatile("cp.async.cg.shared.global [%0], [%1], 16;" :: "r"(dst), "l"(src));
}
#define CP_COMMIT()  asm volatile("cp.async.commit_group;" ::: "memory")
#define CP_WAITG(n)  asm volatile("cp.async.wait_group %0;" :: "n"(n) : "memory")

#define LDSM4(r, a) \
    asm volatile("ldmatrix.sync.aligned.m8n8.x4.shared.b16 {%0,%1,%2,%3}, [%4];" \
        : "=r"((r)[0]), "=r"((r)[1]), "=r"((r)[2]), "=r"((r)[3]) : "r"(a))

#define MMA_TF32(d, a, b0, b1) \
    asm volatile("mma.sync.aligned.m16n8k8.row.col.f32.tf32.tf32.f32 " \
        "{%0,%1,%2,%3}, {%4,%5,%6,%7}, {%8,%9}, {%0,%1,%2,%3};" \
        : "+f"((d)[0]), "+f"((d)[1]), "+f"((d)[2]), "+f"((d)[3]) \
        : "r"((a)[0]), "r"((a)[1]), "r"((a)[2]), "r"((a)[3]), "r"(b0), "r"(b1))

// ---------------------------------------------------------------------------
// Fused weight transposes + tf32 RN rounding (one launch, 3 segments), N = 512
// ---------------------------------------------------------------------------
__global__ __launch_bounds__(256) void transposeAll(
    const float* __restrict__ Wq, float* __restrict__ wqT,
    const float* __restrict__ Ws, float* __restrict__ wsT,
    const float* __restrict__ Wo, float* __restrict__ woT)
{
    __shared__ float t[32][33];
    int bid = blockIdx.x;
    const float* W; float* WT; int K;
    if (bid < 256)       { W = Wq; WT = wqT; K = 512;  }
    else if (bid < 1280) { W = Ws; WT = wsT; K = 2048; bid -= 256;  }
    else                 { W = Wo; WT = woT; K = 1024; bid -= 1280; }
    int k0 = (bid >> 4) * 32, n0 = (bid & 15) * 32;
    int x = threadIdx.x & 31, y = threadIdx.x >> 5;
#pragma unroll
    for (int i = 0; i < 32; i += 8)
        t[y + i][x] = W[(long)(k0 + y + i) * 512 + n0 + x];
    __syncthreads();
#pragma unroll
    for (int i = 0; i < 32; i += 8) {
        float v = t[x][y + i];
        asm("cvt.rna.tf32.f32 %0, %0;" : "+f"(v));
        WT[(long)(n0 + y + i) * K + k0 + x] = v;
    }
}

// ---------------------------------------------------------------------------
// init: out[r][c] = bias[c]  (pre-bias for atomic split-K accumulation)
// ---------------------------------------------------------------------------
__global__ __launch_bounds__(256) void initOut(float* __restrict__ out,
                                               const float* __restrict__ bias) {
    int i = blockIdx.x * 256 + threadIdx.x;        // over 131072 float4
    float4 b = ((const float4*)bias)[i & 127];
    ((float4*)out)[i] = b;
}

// ---------------------------------------------------------------------------
// tf32 mma.sync GEMM: C[M,512] (+)= A @ WT^T [+ bias]
//   CTA tile 64x64, BK=32, 128 threads, 3-stage cp.async pipeline, 48KB smem
//   -> 4 CTAs/SM. Epilogue: store(+bias) or atomicAdd (split-K).
// ---------------------------------------------------------------------------
struct GD {
    const float* A0; const float* A1;
    int rowSplit;       // rows >= rowSplit come from A1
    int lda;            // A row stride (floats)
    const float* WT;    // n-major weights, row stride ldw
    int ldw;
    const float* bias;  // used only when atomicFlag == 0
    float* C;           // row stride 512
    int K;              // iteration extent (multiple of 32)
    int Mreal;
    int atomicFlag;
};

#define STG_BYTES 16384u
#define ABASE(s) ((s) * STG_BYTES)
#define BBASE(s) ((s) * STG_BYTES + 8192u)
#define DSMEM    49152

extern __shared__ __align__(128) float dynsm[];

__global__ __launch_bounds__(128) void gemm_mma(GD ga, GD gb, int tilesA)
{
    const bool first = (blockIdx.x < (unsigned)tilesA);
    GD g = first ? ga : gb;
    const int lbid = first ? blockIdx.x : blockIdx.x - tilesA;

    const int bm = (lbid >> 3) * 64;       // tilesN = 8
    const int bn = (lbid & 7) * 64;
    const int tid  = threadIdx.x;
    const int lane = tid & 31;
    const int wid  = tid >> 5;
    const int wm   = (wid & 1) * 32;
    const int wn   = (wid >> 1) * 32;
    const int T = g.K >> 5;
    const int Mlast = g.Mreal - 1;

    const uint32_t smem = s2u(dynsm);

    const int lr     = lane & 7;
    const int rowoff = ((lane >> 3) & 1) * 8;
    const int coff   = lane >> 4;
    const int arow   = wm + rowoff + lr;
    const int brow   = wn + rowoff + lr;

    float acc[2][4][4];
#pragma unroll
    for (int mi = 0; mi < 2; mi++)
#pragma unroll
        for (int ni = 0; ni < 4; ni++)
#pragma unroll
            for (int j = 0; j < 4; j++) acc[mi][ni][j] = 0.f;

    auto issue_tile = [&](int t, int s) {
        const int k0 = t << 5;
#pragma unroll
        for (int i = 0; i < 4; i++) {          // A: 512 chunks
            int idx = tid + (i << 7);
            int r = idx >> 3, c = idx & 7;
            uint32_t dst = smem + ABASE(s) + (uint32_t)((r << 3) + (c ^ (r & 7))) * 16u;
            int gr = bm + r; if (gr > Mlast) gr = Mlast;
            const float* p = (gr < g.rowSplit)
                ? g.A0 + (long)gr * g.lda
                : g.A1 + (long)(gr - g.rowSplit) * g.lda;
            cp16(dst, p + k0 + c * 4);
        }
#pragma unroll
        for (int i = 0; i < 4; i++) {          // B: 512 chunks
            int idx = tid + (i << 7);
            int r = idx >> 3, c = idx & 7;
            uint32_t dst = smem + BBASE(s) + (uint32_t)((r << 3) + (c ^ (r & 7))) * 16u;
            cp16(dst, g.WT + (long)(bn + r) * g.ldw + k0 + c * 4);
        }
    };

    issue_tile(0, 0); CP_COMMIT();
    issue_tile(1, 1); CP_COMMIT();

    int s = 0;
    for (int t = 0; t < T; t++) {
        CP_WAITG(1);                 // tile t resident
        __syncthreads();             // all warps done with tile t-1's smem
        int sn = s + 2; if (sn >= 3) sn -= 3;
        if (t + 2 < T) issue_tile(t + 2, sn);
        CP_COMMIT();

        const uint32_t ab = smem + ABASE(s);
        const uint32_t bb = smem + BBASE(s);
#pragma unroll
        for (int ks = 0; ks < 4; ks++) {
            uint32_t a[2][4], bf[2][4];
#pragma unroll
            for (int mi = 0; mi < 2; mi++) {
                uint32_t ad = ab + (uint32_t)(arow + mi * 16) * 128u
                                 + (uint32_t)(((ks << 1) + coff) ^ lr) * 16u;
                LDSM4(a[mi], ad);
            }
#pragma unroll
            for (int ng = 0; ng < 2; ng++) {
                uint32_t bd = bb + (uint32_t)(brow + ng * 16) * 128u
                                 + (uint32_t)(((ks << 1) + coff) ^ lr) * 16u;
                LDSM4(bf[ng], bd);
            }
#pragma unroll
            for (int mi = 0; mi < 2; mi++)
#pragma unroll
                for (int j = 0; j < 4; j++)
                    asm("cvt.rna.tf32.f32 %0, %0;" : "+r"(a[mi][j]));
#pragma unroll
            for (int mi = 0; mi < 2; mi++)
#pragma unroll
                for (int ni = 0; ni < 4; ni++) {
                    int ng = ni >> 1, sel = ni & 1;
                    MMA_TF32(acc[mi][ni], a[mi], bf[ng][sel], bf[ng][sel + 2]);
                }
        }
        if (++s >= 3) s -= 3;
    }

    // ---- epilogue ----
    const int r0 = bm + wm + (lane >> 2);
    const int cb = bn + wn + 2 * (lane & 3);
    if (!g.atomicFlag) {
#pragma unroll
        for (int ni = 0; ni < 4; ni++) {
            int col = cb + ni * 8;
            float2 bv = *(const float2*)&g.bias[col];
#pragma unroll
            for (int mi = 0; mi < 2; mi++) {
                int r = r0 + mi * 16;
                if (r < g.Mreal) {
                    float2 v0 = { acc[mi][ni][0] + bv.x, acc[mi][ni][1] + bv.y };
                    *(float2*)&g.C[(long)r * 512 + col] = v0;
                }
                if (r + 8 < g.Mreal) {
                    float2 v1 = { acc[mi][ni][2] + bv.x, acc[mi][ni][3] + bv.y };
                    *(float2*)&g.C[(long)(r + 8) * 512 + col] = v1;
                }
            }
        }
    } else {
#pragma unroll
        for (int ni = 0; ni < 4; ni++) {
            int col = cb + ni * 8;
#pragma unroll
            for (int mi = 0; mi < 2; mi++) {
                int r = r0 + mi * 16;
                if (r < g.Mreal) {
                    atomicAdd(&g.C[(long)r * 512 + col],     acc[mi][ni][0]);
                    atomicAdd(&g.C[(long)r * 512 + col + 1], acc[mi][ni][1]);
                }
                if (r + 8 < g.Mreal) {
                    atomicAdd(&g.C[(long)(r + 8) * 512 + col],     acc[mi][ni][2]);
                    atomicAdd(&g.C[(long)(r + 8) * 512 + col + 1], acc[mi][ni][3]);
                }
            }
        }
    }
}

// ---------------------------------------------------------------------------
// Attention middle (factorized softmax), gmem-direct streaming, fp32.
// ---------------------------------------------------------------------------
__global__ __launch_bounds__(256) void attn2(
    const float* __restrict__ gq, const float* __restrict__ gkey,
    float* __restrict__ gctx)
{
    const int b  = blockIdx.y;
    const int l0 = blockIdx.x * 8;
    const int tid = threadIdx.x;
    const int lane = tid & 31;
    const int wid  = tid >> 5;

    __shared__ __align__(16) float qsm[8 * 512];
    __shared__ __align__(16) float ssc[8 * 200];
    __shared__ __align__(16) float wts[200 * 8];

    const float* keyS = gkey + (long)(b * SS) * HD;
    const float* keyT = gkey + (long)(BB * SS + b * TT) * HD;

#pragma unroll
    for (int i = 0; i < 4; i++) {
        int idx = tid + (i << 8);
        int l = idx >> 7, c4 = idx & 127;
        ((float4*)qsm)[l * 128 + c4] =
            __ldg((const float4*)(gq + (long)(b * LL + l0 + l) * HD) + c4);
    }
    __syncthreads();

    // ---- phase 1: qs/qt dots ----
    if (tid < 200) {
        const float* kr = (tid < SS) ? keyS + (long)tid * HD
                                     : keyT + (long)(tid - SS) * HD;
        float acc[8];
#pragma unroll
        for (int l = 0; l < 8; l++) acc[l] = 0.f;
#pragma unroll 2
        for (int k4 = 0; k4 < 128; k4++) {
            float4 kv = __ldg((const float4*)kr + k4);
#pragma unroll
            for (int l = 0; l < 8; l++) {
                float4 qv = *(const float4*)&qsm[l * 512 + k4 * 4];
                acc[l] += kv.x * qv.x + kv.y * qv.y + kv.z * qv.z + kv.w * qv.w;
            }
        }
#pragma unroll
        for (int l = 0; l < 8; l++) ssc[l * 200 + tid] = acc[l];
    }
    __syncthreads();

    // ---- phase 3: factorized softmax (warp l = wid) ----
    {
        const int l = wid;
        const float sc1 = 1.0f / 32.0f;
        const float rs2 = 0.70710678118654752f;

        float vb[4], m = -1e30f;
#pragma unroll
        for (int ii = 0; ii < 4; ii++) {
            int j = lane + 32 * ii;
            vb[ii] = (j < SS) ? ssc[l * 200 + j] * sc1 : -1e30f;
            m = fmaxf(m, vb[ii]);
        }
#pragma unroll
        for (int off = 16; off; off >>= 1) m = fmaxf(m, __shfl_xor_sync(0xffffffffu, m, off));
        float sum = 0.f;
#pragma unroll
        for (int ii = 0; ii < 4; ii++) {
            int j = lane + 32 * ii;
            if (j < SS) { vb[ii] = __expf(vb[ii] - m); sum += vb[ii]; }
        }
#pragma unroll
        for (int off = 16; off; off >>= 1) sum += __shfl_xor_sync(0xffffffffu, sum, off);
        float inv = rs2 / sum;
#pragma unroll
        for (int ii = 0; ii < 4; ii++) {
            int j = lane + 32 * ii;
            if (j < SS) wts[j * 8 + l] = vb[ii] * inv;
        }

        m = -1e30f;
#pragma unroll
        for (int ii = 0; ii < 4; ii++) {
            int j = lane + 32 * ii;
            vb[ii] = (j < TT) ? -ssc[l * 200 + SS + j] * sc1 : -1e30f;
            m = fmaxf(m, vb[ii]);
        }
#pragma unroll
        for (int off = 16; off; off >>= 1) m = fmaxf(m, __shfl_xor_sync(0xffffffffu, m, off));
        sum = 0.f;
#pragma unroll
        for (int ii = 0; ii < 4; ii++) {
            int j = lane + 32 * ii;
            if (j < TT) { vb[ii] = __expf(vb[ii] - m); sum += vb[ii]; }
        }
#pragma unroll
        for (int off = 16; off; off >>= 1) sum += __shfl_xor_sync(0xffffffffu, sum, off);
        inv = -rs2 / sum;
#pragma unroll
        for (int ii = 0; ii < 4; ii++) {
            int j = lane + 32 * ii;
            if (j < TT) wts[(SS + j) * 8 + l] = vb[ii] * inv;
        }
    }
    __syncthreads();

    // ---- phase 4: ctx = w @ keys (outer-product streaming) ----
    {
        const int grp = tid >> 7;
        const int ci  = tid & 127;
        const int lb  = grp * 4;
        float4 a0 = {0,0,0,0}, a1 = {0,0,0,0}, a2 = {0,0,0,0}, a3 = {0,0,0,0};

#pragma unroll 4
        for (int j = 0; j < SS; j++) {
            float4 kv = __ldg((const float4*)(keyS + (long)j * HD) + ci);
            float4 w4 = *(const float4*)&wts[j * 8 + lb];
            a0.x += w4.x * kv.x; a0.y += w4.x * kv.y; a0.z += w4.x * kv.z; a0.w += w4.x * kv.w;
            a1.x += w4.y * kv.x; a1.y += w4.y * kv.y; a1.z += w4.y * kv.z; a1.w += w4.y * kv.w;
            a2.x += w4.z * kv.x; a2.y += w4.z * kv.y; a2.z += w4.z * kv.z; a2.w += w4.z * kv.w;
            a3.x += w4.w * kv.x; a3.y += w4.w * kv.y; a3.z += w4.w * kv.z; a3.w += w4.w * kv.w;
        }
#pragma unroll 4
        for (int j = 0; j < TT; j++) {
            float4 kv = __ldg((const float4*)(keyT + (long)j * HD) + ci);
            float4 w4 = *(const float4*)&wts[(SS + j) * 8 + lb];
            a0.x += w4.x * kv.x; a0.y += w4.x * kv.y; a0.z += w4.x * kv.z; a0.w += w4.x * kv.w;
            a1.x += w4.y * kv.x; a1.y += w4.y * kv.y; a1.z += w4.y * kv.z; a1.w += w4.y * kv.w;
            a2.x += w4.z * kv.x; a2.y += w4.z * kv.y; a2.z += w4.z * kv.z; a2.w += w4.z * kv.w;
            a3.x += w4.w * kv.x; a3.y += w4.w * kv.y; a3.z += w4.w * kv.z; a3.w += w4.w * kv.w;
        }

        float* base = gctx + (long)(b * LL + l0 + lb) * HD + ci * 4;
        *(float4*)(base + 0 * HD) = a0;
        *(float4*)(base + 1 * HD) = a1;
        *(float4*)(base + 2 * HD) = a2;
        *(float4*)(base + 3 * HD) = a3;
    }
}

// ---------------------------------------------------------------------------
extern "C" void kernel_launch(void* const* d_in, const int* in_sizes, int n_in,
                              void* d_out, int out_size)
{
    const float* query = (const float*)d_in[0];
    const float* src   = (const float*)d_in[1];
    const float* trg   = (const float*)d_in[2];
    const float* Wq    = (const float*)d_in[3];
    const float* bq    = (const float*)d_in[4];
    const float* Ws    = (const float*)d_in[5];
    const float* bs    = (const float*)d_in[6];
    const float* Wo    = (const float*)d_in[7];
    const float* bo    = (const float*)d_in[8];
    float* out = (float*)d_out;

    float *qbuf, *keybuf, *ctxbuf, *wqT, *wsT, *woT;
    cudaGetSymbolAddress((void**)&qbuf,   g_q);
    cudaGetSymbolAddress((void**)&keybuf, g_key);
    cudaGetSymbolAddress((void**)&ctxbuf, g_ctx);
    cudaGetSymbolAddress((void**)&wqT,    g_wqT);
    cudaGetSymbolAddress((void**)&wsT,    g_wsT);
    cudaGetSymbolAddress((void**)&woT,    g_woT);

    cudaFuncSetAttribute(gemm_mma, cudaFuncAttributeMaxDynamicSharedMemorySize, DSMEM);

    // Weight transposes (tf32 RN pre-rounding) + bias pre-init of out
    transposeAll<<<1792, 256>>>(Wq, wqT, Ws, wsT, Wo, woT);
    initOut<<<512, 256>>>(out, bo);

    // Fused key-proj (first: long K) + q-proj
    GD dKey = { src,   trg,   BB * SS, FD, wsT, FD, bs, keybuf, FD, BB * (SS + TT), 0 };
    GD dQ   = { query, query, 1 << 30, QD, wqT, QD, bq, qbuf,   QD, BB * LL, 0 };
    int tKey = 26 * 8;    // 208
    int tQ   = 16 * 8;    // 128
    gemm_mma<<<tKey + tQ, 128, DSMEM>>>(dKey, dQ, tKey);

    // Attention middle (factorized softmax)
    attn2<<<dim3(LL / 8, BB), 256>>>(qbuf, keybuf, ctxbuf);

    // Out-proj as split-K at the concat boundary: out += query@Wo[:512] + ctx@Wo[512:]
    GD dO1 = { query,  query,  1 << 30, QD, woT,       QD + HD, 0, out, QD, BB * LL, 1 };
    GD dO2 = { ctxbuf, ctxbuf, 1 << 30, HD, woT + QD,  QD + HD, 0, out, HD, BB * LL, 1 };
    gemm_mma<<<256, 128, DSMEM>>>(dO1, dO2, 128);
}